// round 15
// baseline (speedup 1.0000x reference)
#include <cuda_runtime.h>
#include <math.h>

#define N_    4096
#define V_    2
#define W_    32
#define H_    16
#define M_    512
#define MH_   256          // M_/2 : packed pair count
#define EPSF  1e-6f
#define PIF   3.14159265358979323846f
#define SQPIF 1.7724538509055160f   // sqrt(pi)

typedef unsigned long long u64;

// ---------- packed f32x2 helpers (sm_103a FFMA2 path) ----------
__device__ __forceinline__ u64 pk2(float a, float b) {
    u64 r; asm("mov.b64 %0, {%1, %2};" : "=l"(r) : "f"(a), "f"(b)); return r;
}
__device__ __forceinline__ float2 upk2(u64 v) {
    float2 r; asm("mov.b64 {%0, %1}, %2;" : "=f"(r.x), "=f"(r.y) : "l"(v)); return r;
}
__device__ __forceinline__ u64 fma2(u64 a, u64 b, u64 c) {
    u64 d; asm("fma.rn.f32x2 %0, %1, %2, %3;" : "=l"(d) : "l"(a), "l"(b), "l"(c)); return d;
}
__device__ __forceinline__ u64 mul2(u64 a, u64 b) {
    u64 d; asm("mul.rn.f32x2 %0, %1, %2;" : "=l"(d) : "l"(a), "l"(b)); return d;
}
__device__ __forceinline__ u64 add2(u64 a, u64 b) {
    u64 d; asm("add.rn.f32x2 %0, %1, %2;" : "=l"(d) : "l"(a), "l"(b)); return d;
}
__device__ __forceinline__ float rsq_fast(float x) {
    float r; asm("rsqrt.approx.f32 %0, %1;" : "=f"(r) : "f"(x)); return r;
}
__device__ __forceinline__ float rcp_fast(float x) {
    float r; asm("rcp.approx.f32 %0, %1;" : "=f"(r) : "f"(x)); return r;
}

#define ABSM 0x7FFFFFFF7FFFFFFFULL

// Interleaved per-pair table: 48 bytes per pair p = samples (2p, 2p+1).
// Direction components stored PRE-HALVED (0.5*l) - exact exponent shift that,
// combined with halved v, makes NdotH/VdotH come out at unit scale for free.
//   [3p+0] = (0.5*lx pair, 0.5*ly pair)
//   [3p+1] = (0.5*lz pair, LiR*sa pair)
//   [3p+2] = (LiG*sa pair, LiB*sa pair)
__device__ ulonglong2 g_tab[MH_ * 3];

__global__ void hdr_prep_kernel(const float* __restrict__ env_map)
{
    const int p = blockIdx.x * blockDim.x + threadIdx.x;
    if (p >= MH_) return;
    float lx[2], ly[2], lz[2], er[2], eg[2], eb[2];
    #pragma unroll
    for (int h = 0; h < 2; ++h) {
        const int m = 2 * p + h;
        const int j = m >> 5;          // theta index (H)
        const int i = m & (W_ - 1);    // phi index (W)
        const float theta = ((float)j + 0.5f) * (1.0f / (float)H_) * PIF;
        const float phi   = ((float)i + 0.5f) * (1.0f / (float)W_) * (2.0f * PIF) + 0.5f * PIF;
        const float st = __sinf(theta), ct = __cosf(theta);
        const float sp = __sinf(phi),   cp = __cosf(phi);
        const float sa = st * ((PIF / (float)H_) * (2.0f * PIF / (float)W_));
        // bilinear grid_sample degenerates to exact texel fetch: Li = env_map[0, i, j, :]
        const float* e = env_map + (i * H_ + j) * 3;
        lx[h] = 0.5f * (st * cp);  ly[h] = 0.5f * ct;  lz[h] = 0.5f * (-st * sp);
        er[h] = e[0] * sa; eg[h] = e[1] * sa; eb[h] = e[2] * sa;
    }
    float4* f = reinterpret_cast<float4*>(g_tab);
    f[3 * p + 0] = make_float4(lx[0], lx[1], ly[0], ly[1]);
    f[3 * p + 1] = make_float4(lz[0], lz[1], er[0], er[1]);
    f[3 * p + 2] = make_float4(eg[0], eg[1], eb[0], eb[1]);
}

__global__ __launch_bounds__(128) void hdr_render_kernel(
    const float* __restrict__ normals,
    const float* __restrict__ albedo,
    const float* __restrict__ metallic,
    const float* __restrict__ smoothness,
    const float* __restrict__ viewdirs,
    const float* __restrict__ env_vis,
    float* __restrict__ out)
{
    const int tid   = threadIdx.x;
    const int gwarp = (blockIdx.x * 128 + tid) >> 5;   // pair = n*V + vi
    const int lane  = tid & 31;
    const int n     = gwarp >> 1;

    // Prefetch ALL vis loads first: MLP=8 on the one DRAM-bound stream.
    const u64* __restrict__ visq = (const u64*)(env_vis + n * M_) + lane;
    u64 visv[MH_ / 32];
    #pragma unroll
    for (int kIt = 0; kIt < MH_ / 32; ++kIt) visv[kIt] = visq[32 * kIt];

    // ---- warp-invariant scalar setup ----
    float nx = normals[n * 3 + 0];
    float ny = normals[n * 3 + 1];
    float nz = normals[n * 3 + 2];
    {
        const float inv = rsqrtf(fmaxf(fmaf(nx, nx, fmaf(ny, ny, nz * nz)), 1e-24f));
        nx *= inv; ny *= inv; nz *= inv;
    }
    const float* vd = viewdirs + gwarp * 3;
    float vx = vd[0], vy = vd[1], vz = vd[2];
    {
        const float inv = rsqrtf(fmaxf(fmaf(vx, vx, fmaf(vy, vy, vz * vz)), 1e-24f));
        vx *= inv; vy *= inv; vz *= inv;
    }

    const float met    = metallic[n];
    const float rough  = 1.0f - smoothness[n];
    const float alpha  = rough * rough;
    const float alpha2 = alpha * alpha;
    const float a2m1   = alpha2 - 1.0f;
    const float k      = 0.5f * alpha;
    const float omk    = 1.0f - k;
    const float k_eps  = k + EPSF;

    const float ar = albedo[n * 3 + 0];
    const float ag = albedo[n * 3 + 1];
    const float ab = albedo[n * 3 + 2];
    const float f0r = fmaf(ar - 0.04f, met, 0.04f);
    const float f0g = fmaf(ag - 0.04f, met, 0.04f);
    const float f0b = fmaf(ab - 0.04f, met, 0.04f);

    const float ndv_raw = fmaf(nx, vx, fmaf(ny, vy, nz * vz));
    const float NdotV   = fmaxf(ndv_raw, EPSF);
    const float Gv      = NdotV / fmaf(NdotV, omk, k_eps);
    const float a2Gv    = alpha2 * Gv;

    // den2*den3 expanded: (omk*NdL + k_eps)(4NdV*NdL + EPS) = c2*NdL^2 + c1*NdL + c0
    const float c2 = 4.0f * NdotV * omk;
    const float c1 = fmaf(4.0f * NdotV, k_eps, omk * EPSF);
    const float c0 = k_eps * EPSF;

    const float dcom = (1.0f - met) * (1.0f / PIF);
    const float dR = dcom * ar, dG = dcom * ag, dB = dcom * ab;

    // ---- packed (splat) constants (23 u64) ----
    const u64 VX2 = pk2(0.5f * vx, 0.5f * vx);   // halved v (matches halved table)
    const u64 VY2 = pk2(0.5f * vy, 0.5f * vy);
    const u64 VZ2 = pk2(0.5f * vz, 0.5f * vz);
    const u64 NX2 = pk2(nx, nx), NY2 = pk2(ny, ny), NZ2 = pk2(nz, nz);
    const u64 NDVRH2 = pk2(0.5f * ndv_raw, 0.5f * ndv_raw);
    const u64 ONE2   = pk2(1.0f, 1.0f);
    const u64 NEG1_2 = pk2(-1.0f, -1.0f);
    const u64 EPS2   = pk2(EPSF, EPSF);
    const u64 TINY2  = pk2(1e-24f, 1e-24f);
    // sqrt(pi) fold: DD' = sqrt(pi)*DD ; DEN1 = DD'^2 + EPS
    const float qsp  = SQPIF * 0.25f * a2m1;
    const u64 A2M1QP2 = pk2(qsp, qsp);
    const u64 SQPI2   = pk2(SQPIF, SQPIF);
    const u64 C2_2   = pk2(c2, c2);
    const u64 C1_2   = pk2(c1, c1);
    const u64 C0_2   = pk2(c0, c0);
    const u64 A2GV2  = pk2(a2Gv, a2Gv);
    const u64 F0R2 = pk2(f0r, f0r), F0G2 = pk2(f0g, f0g), F0B2 = pk2(f0b, f0b);
    const u64 DR2 = pk2(dR, dR), DG2 = pk2(dG, dG), DB2 = pk2(dB, dB);

    const ulonglong2* __restrict__ tb = g_tab + 3 * lane;

    u64 ACR = 0ull, ACG = 0ull, ACB = 0ull;   // packed (0.f, 0.f)

    #pragma unroll
    for (int kIt = 0; kIt < MH_ / 32; ++kIt) {
        // table loads: L1-resident (12KB shared by all warps), immediate offsets
        const ulonglong2 t0 = tb[3 * 32 * kIt + 0];
        const ulonglong2 t1 = tb[3 * 32 * kIt + 1];
        const ulonglong2 t2 = tb[3 * 32 * kIt + 2];
        const u64 VIS = visv[kIt];
        const u64 LX = t0.x, LY = t0.y;   // 0.5*l components
        const u64 LZ = t1.x, LR = t1.y;
        const u64 LG = t2.x, LB = t2.y;

        // half vector at half scale: H' = 0.5*(v+l); HH' = |h|^2/4 (exact scaling)
        const u64 HX = add2(LX, VX2);
        const u64 HY = add2(LY, VY2);
        const u64 HZ = add2(LZ, VZ2);
        const u64 HH = fma2(HX, HX, fma2(HY, HY, mul2(HZ, HZ)));
        const u64 HHc = add2(HH, TINY2);
        const float2 hh = upk2(HHc);
        const u64 HINV = pk2(rsq_fast(hh.x), rsq_fast(hh.y));   // = 2/|h| exactly

        // NL' = (n.l)/2 ; A = NL'+|NL'| = max(n.l,0) ; NdotL = A + EPS
        const u64 NL  = fma2(LX, NX2, fma2(LY, NY2, mul2(LZ, NZ2)));
        const u64 NDL = add2(add2(NL, NL & ABSM), EPS2);

        // n.h at half scale: NHR' = (n.l + n.v)/2 ; NH = NHR'*HINV = NdotH exactly
        const u64 NHR = add2(NL, NDVRH2);
        const u64 NH  = mul2(NHR, HINV);
        const u64 SSx = add2(NH, NH & ABSM);       // 2*max(NdotH,0)
        const u64 SS2 = mul2(SSx, SSx);
        const u64 DDp = fma2(SS2, A2M1QP2, SQPI2); // sqrt(pi)*(q*SS^2 + 1)
        const u64 DEN1 = fma2(DDp, DDp, EPS2);     // pi*DD^2 + EPS

        const u64 DEN23 = fma2(fma2(C2_2, NDL, C1_2), NDL, C0_2);
        const u64 DEN   = mul2(DEN1, DEN23);
        const float2 dv = upk2(DEN);
        const u64 RCPD  = pk2(rcp_fast(dv.x), rcp_fast(dv.y));
        const u64 S     = mul2(mul2(A2GV2, NDL), RCPD);

        // Fresnel: VdotH = |h|/2 = HHc'*HINV' exactly; t = 1 - VdotH
        const u64 VHs = mul2(HHc, HINV);
        const u64 Tt  = fma2(VHs, NEG1_2, ONE2);
        const u64 T2  = mul2(Tt, Tt);
        const u64 P5  = mul2(mul2(T2, T2), Tt);
        const u64 OMP5 = fma2(P5, NEG1_2, ONE2);   // 1 - p5 (shared by RGB)

        const u64 Wt = mul2(VIS, NDL);   // sa pre-folded into Li tables

        // FrC = f0C*(1-p5) + p5 ; S - dC = fma(dC, -1, S)
        const u64 FR = fma2(F0R2, OMP5, P5);
        const u64 FG = fma2(F0G2, OMP5, P5);
        const u64 FB = fma2(F0B2, OMP5, P5);
        const u64 SMR = fma2(DR2, NEG1_2, S);
        const u64 SMG = fma2(DG2, NEG1_2, S);
        const u64 SMB = fma2(DB2, NEG1_2, S);

        ACR = fma2(mul2(LR, Wt), fma2(FR, SMR, DR2), ACR);
        ACG = fma2(mul2(LG, Wt), fma2(FG, SMG, DG2), ACG);
        ACB = fma2(mul2(LB, Wt), fma2(FB, SMB, DB2), ACB);
    }

    // collapse packed halves, then warp tree-reduce
    const float2 cr = upk2(ACR);
    const float2 cg = upk2(ACG);
    const float2 cb = upk2(ACB);
    float accR = cr.x + cr.y;
    float accG = cg.x + cg.y;
    float accB = cb.x + cb.y;

    #pragma unroll
    for (int off = 16; off > 0; off >>= 1) {
        accR += __shfl_down_sync(0xffffffffu, accR, off);
        accG += __shfl_down_sync(0xffffffffu, accG, off);
        accB += __shfl_down_sync(0xffffffffu, accB, off);
    }

    if (lane == 0) {
        float* o = out + gwarp * 3;
        o[0] = accR;
        o[1] = accG;
        o[2] = accB;
    }
}

extern "C" void kernel_launch(void* const* d_in, const int* in_sizes, int n_in,
                              void* d_out, int out_size)
{
    const float* normals    = (const float*)d_in[0];
    const float* albedo     = (const float*)d_in[1];
    const float* metallic   = (const float*)d_in[2];
    const float* smoothness = (const float*)d_in[3];
    const float* viewdirs   = (const float*)d_in[4];
    const float* env_vis    = (const float*)d_in[5];
    const float* env_map    = (const float*)d_in[6];
    float* out = (float*)d_out;

    hdr_prep_kernel<<<8, 32>>>(env_map);    // parallel prep, MUFU sin/cos

    const int pairs   = N_ * V_;                // 8192 warps
    const int threads = 128;                    // 4 warps/block
    const int blocks  = pairs * 32 / threads;   // 2048

    hdr_render_kernel<<<blocks, threads>>>(normals, albedo, metallic, smoothness,
                                           viewdirs, env_vis, out);
}

// round 16
// speedup vs baseline: 1.7125x; 1.7125x over previous
#include <cuda_runtime.h>
#include <math.h>

#define N_    4096
#define V_    2
#define W_    32
#define H_    16
#define M_    512
#define MH_   256          // M_/2 : packed pair count
#define EPSF  1e-6f
#define PIF   3.14159265358979323846f
#define SQPIF 1.7724538509055160f   // sqrt(pi)

typedef unsigned long long u64;

// ---------- packed f32x2 helpers (sm_103a FFMA2 path) ----------
__device__ __forceinline__ u64 pk2(float a, float b) {
    u64 r; asm("mov.b64 %0, {%1, %2};" : "=l"(r) : "f"(a), "f"(b)); return r;
}
__device__ __forceinline__ float2 upk2(u64 v) {
    float2 r; asm("mov.b64 {%0, %1}, %2;" : "=f"(r.x), "=f"(r.y) : "l"(v)); return r;
}
__device__ __forceinline__ u64 fma2(u64 a, u64 b, u64 c) {
    u64 d; asm("fma.rn.f32x2 %0, %1, %2, %3;" : "=l"(d) : "l"(a), "l"(b), "l"(c)); return d;
}
__device__ __forceinline__ u64 mul2(u64 a, u64 b) {
    u64 d; asm("mul.rn.f32x2 %0, %1, %2;" : "=l"(d) : "l"(a), "l"(b)); return d;
}
__device__ __forceinline__ u64 add2(u64 a, u64 b) {
    u64 d; asm("add.rn.f32x2 %0, %1, %2;" : "=l"(d) : "l"(a), "l"(b)); return d;
}
__device__ __forceinline__ float rsq_fast(float x) {
    float r; asm("rsqrt.approx.f32 %0, %1;" : "=f"(r) : "f"(x)); return r;
}
__device__ __forceinline__ float rcp_fast(float x) {
    float r; asm("rcp.approx.f32 %0, %1;" : "=f"(r) : "f"(x)); return r;
}

#define ABSM 0x7FFFFFFF7FFFFFFFULL

// Interleaved per-pair table: 48 bytes per pair p = samples (2p, 2p+1).
// Direction components stored PRE-HALVED (0.5*l) - exact exponent shift that,
// combined with halved v, makes NdotH/VdotH come out at unit scale for free.
//   [3p+0] = (0.5*lx pair, 0.5*ly pair)
//   [3p+1] = (0.5*lz pair, LiR*sa pair)
//   [3p+2] = (LiG*sa pair, LiB*sa pair)
__device__ ulonglong2 g_tab[MH_ * 3];

__global__ void hdr_prep_kernel(const float* __restrict__ env_map)
{
    const int p = blockIdx.x * blockDim.x + threadIdx.x;
    if (p >= MH_) return;
    float lx[2], ly[2], lz[2], er[2], eg[2], eb[2];
    #pragma unroll
    for (int h = 0; h < 2; ++h) {
        const int m = 2 * p + h;
        const int j = m >> 5;          // theta index (H)
        const int i = m & (W_ - 1);    // phi index (W)
        const float theta = ((float)j + 0.5f) * (1.0f / (float)H_) * PIF;
        const float phi   = ((float)i + 0.5f) * (1.0f / (float)W_) * (2.0f * PIF) + 0.5f * PIF;
        const float st = __sinf(theta), ct = __cosf(theta);
        const float sp = __sinf(phi),   cp = __cosf(phi);
        const float sa = st * ((PIF / (float)H_) * (2.0f * PIF / (float)W_));
        // bilinear grid_sample degenerates to exact texel fetch: Li = env_map[0, i, j, :]
        const float* e = env_map + (i * H_ + j) * 3;
        lx[h] = 0.5f * (st * cp);  ly[h] = 0.5f * ct;  lz[h] = 0.5f * (-st * sp);
        er[h] = e[0] * sa; eg[h] = e[1] * sa; eb[h] = e[2] * sa;
    }
    float4* f = reinterpret_cast<float4*>(g_tab);
    f[3 * p + 0] = make_float4(lx[0], lx[1], ly[0], ly[1]);
    f[3 * p + 1] = make_float4(lz[0], lz[1], er[0], er[1]);
    f[3 * p + 2] = make_float4(eg[0], eg[1], eb[0], eb[1]);
}

__global__ __launch_bounds__(128) void hdr_render_kernel(
    const float* __restrict__ normals,
    const float* __restrict__ albedo,
    const float* __restrict__ metallic,
    const float* __restrict__ smoothness,
    const float* __restrict__ viewdirs,
    const float* __restrict__ env_vis,
    float* __restrict__ out)
{
    const int tid   = threadIdx.x;
    const int gwarp = (blockIdx.x * 128 + tid) >> 5;   // pair = n*V + vi
    const int lane  = tid & 31;
    const int n     = gwarp >> 1;

    // Prefetch ALL vis loads first: MLP=8 on the one DRAM-bound stream.
    const u64* __restrict__ visq = (const u64*)(env_vis + n * M_) + lane;
    u64 visv[MH_ / 32];
    #pragma unroll
    for (int kIt = 0; kIt < MH_ / 32; ++kIt) visv[kIt] = visq[32 * kIt];

    // ---- warp-invariant scalar setup ----
    float nx = normals[n * 3 + 0];
    float ny = normals[n * 3 + 1];
    float nz = normals[n * 3 + 2];
    {
        const float inv = rsqrtf(fmaxf(fmaf(nx, nx, fmaf(ny, ny, nz * nz)), 1e-24f));
        nx *= inv; ny *= inv; nz *= inv;
    }
    const float* vd = viewdirs + gwarp * 3;
    float vx = vd[0], vy = vd[1], vz = vd[2];
    {
        const float inv = rsqrtf(fmaxf(fmaf(vx, vx, fmaf(vy, vy, vz * vz)), 1e-24f));
        vx *= inv; vy *= inv; vz *= inv;
    }

    const float met    = metallic[n];
    const float rough  = 1.0f - smoothness[n];
    const float alpha  = rough * rough;
    const float alpha2 = alpha * alpha;
    const float a2m1   = alpha2 - 1.0f;
    const float k      = 0.5f * alpha;
    const float omk    = 1.0f - k;
    const float k_eps  = k + EPSF;

    const float ar = albedo[n * 3 + 0];
    const float ag = albedo[n * 3 + 1];
    const float ab = albedo[n * 3 + 2];
    const float f0r = fmaf(ar - 0.04f, met, 0.04f);
    const float f0g = fmaf(ag - 0.04f, met, 0.04f);
    const float f0b = fmaf(ab - 0.04f, met, 0.04f);

    const float ndv_raw = fmaf(nx, vx, fmaf(ny, vy, nz * vz));
    const float NdotV   = fmaxf(ndv_raw, EPSF);
    const float Gv      = NdotV / fmaf(NdotV, omk, k_eps);
    const float a2Gv    = alpha2 * Gv;

    // den2*den3 expanded: (omk*NdL + k_eps)(4NdV*NdL + EPS) = c2*NdL^2 + c1*NdL + c0
    const float c2 = 4.0f * NdotV * omk;
    const float c1 = fmaf(4.0f * NdotV, k_eps, omk * EPSF);
    const float c0 = k_eps * EPSF;

    const float dcom = (1.0f - met) * (1.0f / PIF);
    const float dR = dcom * ar, dG = dcom * ag, dB = dcom * ab;

    // ---- packed (splat) constants (23 u64) ----
    const u64 VX2 = pk2(0.5f * vx, 0.5f * vx);   // halved v (matches halved table)
    const u64 VY2 = pk2(0.5f * vy, 0.5f * vy);
    const u64 VZ2 = pk2(0.5f * vz, 0.5f * vz);
    const u64 NX2 = pk2(nx, nx), NY2 = pk2(ny, ny), NZ2 = pk2(nz, nz);
    const u64 NDVRH2 = pk2(0.5f * ndv_raw, 0.5f * ndv_raw);
    const u64 ONE2   = pk2(1.0f, 1.0f);
    const u64 NEG1_2 = pk2(-1.0f, -1.0f);
    const u64 EPS2   = pk2(EPSF, EPSF);
    const u64 TINY2  = pk2(1e-24f, 1e-24f);
    // sqrt(pi) fold: DD' = sqrt(pi)*DD ; DEN1 = DD'^2 + EPS
    const float qsp  = SQPIF * 0.25f * a2m1;
    const u64 A2M1QP2 = pk2(qsp, qsp);
    const u64 SQPI2   = pk2(SQPIF, SQPIF);
    const u64 C2_2   = pk2(c2, c2);
    const u64 C1_2   = pk2(c1, c1);
    const u64 C0_2   = pk2(c0, c0);
    const u64 A2GV2  = pk2(a2Gv, a2Gv);
    const u64 F0R2 = pk2(f0r, f0r), F0G2 = pk2(f0g, f0g), F0B2 = pk2(f0b, f0b);
    const u64 DR2 = pk2(dR, dR), DG2 = pk2(dG, dG), DB2 = pk2(dB, dB);

    const ulonglong2* __restrict__ tb = g_tab + 3 * lane;

    u64 ACR = 0ull, ACG = 0ull, ACB = 0ull;   // packed (0.f, 0.f)

    #pragma unroll
    for (int kIt = 0; kIt < MH_ / 32; ++kIt) {
        // table loads: L1-resident (12KB shared by all warps), immediate offsets
        const ulonglong2 t0 = tb[3 * 32 * kIt + 0];
        const ulonglong2 t1 = tb[3 * 32 * kIt + 1];
        const ulonglong2 t2 = tb[3 * 32 * kIt + 2];
        const u64 VIS = visv[kIt];
        const u64 LX = t0.x, LY = t0.y;   // 0.5*l components
        const u64 LZ = t1.x, LR = t1.y;
        const u64 LG = t2.x, LB = t2.y;

        // half vector at half scale: H' = 0.5*(v+l); HH' = |h|^2/4 (exact scaling)
        const u64 HX = add2(LX, VX2);
        const u64 HY = add2(LY, VY2);
        const u64 HZ = add2(LZ, VZ2);
        const u64 HH = fma2(HX, HX, fma2(HY, HY, mul2(HZ, HZ)));
        const u64 HHc = add2(HH, TINY2);
        const float2 hh = upk2(HHc);
        const u64 HINV = pk2(rsq_fast(hh.x), rsq_fast(hh.y));   // = 2/|h| exactly

        // NL' = (n.l)/2 ; A = NL'+|NL'| = max(n.l,0) ; NdotL = A + EPS
        const u64 NL  = fma2(LX, NX2, fma2(LY, NY2, mul2(LZ, NZ2)));
        const u64 NDL = add2(add2(NL, NL & ABSM), EPS2);

        // n.h at half scale: NHR' = (n.l + n.v)/2 ; NH = NHR'*HINV = NdotH exactly
        const u64 NHR = add2(NL, NDVRH2);
        const u64 NH  = mul2(NHR, HINV);
        const u64 SSx = add2(NH, NH & ABSM);       // 2*max(NdotH,0)
        const u64 SS2 = mul2(SSx, SSx);
        const u64 DDp = fma2(SS2, A2M1QP2, SQPI2); // sqrt(pi)*(q*SS^2 + 1)
        const u64 DEN1 = fma2(DDp, DDp, EPS2);     // pi*DD^2 + EPS

        const u64 DEN23 = fma2(fma2(C2_2, NDL, C1_2), NDL, C0_2);
        const u64 DEN   = mul2(DEN1, DEN23);
        const float2 dv = upk2(DEN);
        const u64 RCPD  = pk2(rcp_fast(dv.x), rcp_fast(dv.y));
        const u64 S     = mul2(mul2(A2GV2, NDL), RCPD);

        // Fresnel: VdotH = |h|/2 = HHc'*HINV' exactly; t = 1 - VdotH
        const u64 VHs = mul2(HHc, HINV);
        const u64 Tt  = fma2(VHs, NEG1_2, ONE2);
        const u64 T2  = mul2(Tt, Tt);
        const u64 P5  = mul2(mul2(T2, T2), Tt);
        const u64 OMP5 = fma2(P5, NEG1_2, ONE2);   // 1 - p5 (shared by RGB)

        const u64 Wt = mul2(VIS, NDL);   // sa pre-folded into Li tables

        // FrC = f0C*(1-p5) + p5 ; S - dC = fma(dC, -1, S)
        const u64 FR = fma2(F0R2, OMP5, P5);
        const u64 FG = fma2(F0G2, OMP5, P5);
        const u64 FB = fma2(F0B2, OMP5, P5);
        const u64 SMR = fma2(DR2, NEG1_2, S);
        const u64 SMG = fma2(DG2, NEG1_2, S);
        const u64 SMB = fma2(DB2, NEG1_2, S);

        ACR = fma2(mul2(LR, Wt), fma2(FR, SMR, DR2), ACR);
        ACG = fma2(mul2(LG, Wt), fma2(FG, SMG, DG2), ACG);
        ACB = fma2(mul2(LB, Wt), fma2(FB, SMB, DB2), ACB);
    }

    // collapse packed halves, then warp tree-reduce
    const float2 cr = upk2(ACR);
    const float2 cg = upk2(ACG);
    const float2 cb = upk2(ACB);
    float accR = cr.x + cr.y;
    float accG = cg.x + cg.y;
    float accB = cb.x + cb.y;

    #pragma unroll
    for (int off = 16; off > 0; off >>= 1) {
        accR += __shfl_down_sync(0xffffffffu, accR, off);
        accG += __shfl_down_sync(0xffffffffu, accG, off);
        accB += __shfl_down_sync(0xffffffffu, accB, off);
    }

    if (lane == 0) {
        float* o = out + gwarp * 3;
        o[0] = accR;
        o[1] = accG;
        o[2] = accB;
    }
}

extern "C" void kernel_launch(void* const* d_in, const int* in_sizes, int n_in,
                              void* d_out, int out_size)
{
    const float* normals    = (const float*)d_in[0];
    const float* albedo     = (const float*)d_in[1];
    const float* metallic   = (const float*)d_in[2];
    const float* smoothness = (const float*)d_in[3];
    const float* viewdirs   = (const float*)d_in[4];
    const float* env_vis    = (const float*)d_in[5];
    const float* env_map    = (const float*)d_in[6];
    float* out = (float*)d_out;

    hdr_prep_kernel<<<2, 128>>>(env_map);   // parallel prep, MUFU sin/cos

    const int pairs   = N_ * V_;                // 8192 warps
    const int threads = 128;                    // 4 warps/block
    const int blocks  = pairs * 32 / threads;   // 2048

    hdr_render_kernel<<<blocks, threads>>>(normals, albedo, metallic, smoothness,
                                           viewdirs, env_vis, out);
}

// round 17
// speedup vs baseline: 1.7495x; 1.0216x over previous
#include <cuda_runtime.h>
#include <math.h>

#define N_    4096
#define V_    2
#define W_    32
#define H_    16
#define M_    512
#define MH_   256          // M_/2 : packed pair count
#define EPSF  1e-6f
#define PIF   3.14159265358979323846f
#define SQPIF 1.7724538509055160f   // sqrt(pi)

typedef unsigned long long u64;

// ---------- packed f32x2 helpers (sm_103a FFMA2 path) ----------
__device__ __forceinline__ u64 pk2(float a, float b) {
    u64 r; asm("mov.b64 %0, {%1, %2};" : "=l"(r) : "f"(a), "f"(b)); return r;
}
__device__ __forceinline__ float2 upk2(u64 v) {
    float2 r; asm("mov.b64 {%0, %1}, %2;" : "=f"(r.x), "=f"(r.y) : "l"(v)); return r;
}
__device__ __forceinline__ u64 fma2(u64 a, u64 b, u64 c) {
    u64 d; asm("fma.rn.f32x2 %0, %1, %2, %3;" : "=l"(d) : "l"(a), "l"(b), "l"(c)); return d;
}
__device__ __forceinline__ u64 mul2(u64 a, u64 b) {
    u64 d; asm("mul.rn.f32x2 %0, %1, %2;" : "=l"(d) : "l"(a), "l"(b)); return d;
}
__device__ __forceinline__ u64 add2(u64 a, u64 b) {
    u64 d; asm("add.rn.f32x2 %0, %1, %2;" : "=l"(d) : "l"(a), "l"(b)); return d;
}
__device__ __forceinline__ float rsq_fast(float x) {
    float r; asm("rsqrt.approx.f32 %0, %1;" : "=f"(r) : "f"(x)); return r;
}
__device__ __forceinline__ float rcp_fast(float x) {
    float r; asm("rcp.approx.f32 %0, %1;" : "=f"(r) : "f"(x)); return r;
}

#define ABSM 0x7FFFFFFF7FFFFFFFULL

// Interleaved per-pair table: 48 bytes per pair p = samples (2p, 2p+1).
// Direction components stored PRE-HALVED (0.5*l) - exact exponent shift that,
// combined with halved v, makes NdotH/VdotH come out at unit scale for free.
//   [3p+0] = (0.5*lx pair, 0.5*ly pair)
//   [3p+1] = (0.5*lz pair, LiR*sa pair)
//   [3p+2] = (LiG*sa pair, LiB*sa pair)
__device__ ulonglong2 g_tab[MH_ * 3];

__global__ void hdr_prep_kernel(const float* __restrict__ env_map)
{
    const int p = blockIdx.x * blockDim.x + threadIdx.x;
    if (p >= MH_) return;
    float lx[2], ly[2], lz[2], er[2], eg[2], eb[2];
    #pragma unroll
    for (int h = 0; h < 2; ++h) {
        const int m = 2 * p + h;
        const int j = m >> 5;          // theta index (H)
        const int i = m & (W_ - 1);    // phi index (W)
        const float theta = ((float)j + 0.5f) * (1.0f / (float)H_) * PIF;
        const float phi   = ((float)i + 0.5f) * (1.0f / (float)W_) * (2.0f * PIF) + 0.5f * PIF;
        const float st = __sinf(theta), ct = __cosf(theta);
        const float sp = __sinf(phi),   cp = __cosf(phi);
        const float sa = st * ((PIF / (float)H_) * (2.0f * PIF / (float)W_));
        // bilinear grid_sample degenerates to exact texel fetch: Li = env_map[0, i, j, :]
        const float* e = env_map + (i * H_ + j) * 3;
        lx[h] = 0.5f * (st * cp);  ly[h] = 0.5f * ct;  lz[h] = 0.5f * (-st * sp);
        er[h] = e[0] * sa; eg[h] = e[1] * sa; eb[h] = e[2] * sa;
    }
    float4* f = reinterpret_cast<float4*>(g_tab);
    f[3 * p + 0] = make_float4(lx[0], lx[1], ly[0], ly[1]);
    f[3 * p + 1] = make_float4(lz[0], lz[1], er[0], er[1]);
    f[3 * p + 2] = make_float4(eg[0], eg[1], eb[0], eb[1]);
}

__global__ __launch_bounds__(64) void hdr_render_kernel(
    const float* __restrict__ normals,
    const float* __restrict__ albedo,
    const float* __restrict__ metallic,
    const float* __restrict__ smoothness,
    const float* __restrict__ viewdirs,
    const float* __restrict__ env_vis,
    float* __restrict__ out)
{
    const int tid   = threadIdx.x;
    const int gwarp = (blockIdx.x * 64 + tid) >> 5;    // pair = n*V + vi
    const int lane  = tid & 31;
    const int n     = gwarp >> 1;

    // Prefetch ALL vis loads first: MLP=8 on the one DRAM-bound stream.
    const u64* __restrict__ visq = (const u64*)(env_vis + n * M_) + lane;
    u64 visv[MH_ / 32];
    #pragma unroll
    for (int kIt = 0; kIt < MH_ / 32; ++kIt) visv[kIt] = visq[32 * kIt];

    // ---- warp-invariant scalar setup ----
    float nx = normals[n * 3 + 0];
    float ny = normals[n * 3 + 1];
    float nz = normals[n * 3 + 2];
    {
        const float inv = rsqrtf(fmaxf(fmaf(nx, nx, fmaf(ny, ny, nz * nz)), 1e-24f));
        nx *= inv; ny *= inv; nz *= inv;
    }
    const float* vd = viewdirs + gwarp * 3;
    float vx = vd[0], vy = vd[1], vz = vd[2];
    {
        const float inv = rsqrtf(fmaxf(fmaf(vx, vx, fmaf(vy, vy, vz * vz)), 1e-24f));
        vx *= inv; vy *= inv; vz *= inv;
    }

    const float met    = metallic[n];
    const float rough  = 1.0f - smoothness[n];
    const float alpha  = rough * rough;
    const float alpha2 = alpha * alpha;
    const float a2m1   = alpha2 - 1.0f;
    const float k      = 0.5f * alpha;
    const float omk    = 1.0f - k;
    const float k_eps  = k + EPSF;

    const float ar = albedo[n * 3 + 0];
    const float ag = albedo[n * 3 + 1];
    const float ab = albedo[n * 3 + 2];
    const float f0r = fmaf(ar - 0.04f, met, 0.04f);
    const float f0g = fmaf(ag - 0.04f, met, 0.04f);
    const float f0b = fmaf(ab - 0.04f, met, 0.04f);

    const float ndv_raw = fmaf(nx, vx, fmaf(ny, vy, nz * vz));
    const float NdotV   = fmaxf(ndv_raw, EPSF);
    const float Gv      = NdotV / fmaf(NdotV, omk, k_eps);
    const float a2Gv    = alpha2 * Gv;

    // den2*den3 expanded: (omk*NdL + k_eps)(4NdV*NdL + EPS) = c2*NdL^2 + c1*NdL + c0
    const float c2 = 4.0f * NdotV * omk;
    const float c1 = fmaf(4.0f * NdotV, k_eps, omk * EPSF);
    const float c0 = k_eps * EPSF;

    const float dcom = (1.0f - met) * (1.0f / PIF);
    const float dR = dcom * ar, dG = dcom * ag, dB = dcom * ab;

    // ---- packed (splat) constants (23 u64) ----
    const u64 VX2 = pk2(0.5f * vx, 0.5f * vx);   // halved v (matches halved table)
    const u64 VY2 = pk2(0.5f * vy, 0.5f * vy);
    const u64 VZ2 = pk2(0.5f * vz, 0.5f * vz);
    const u64 NX2 = pk2(nx, nx), NY2 = pk2(ny, ny), NZ2 = pk2(nz, nz);
    const u64 NDVRH2 = pk2(0.5f * ndv_raw, 0.5f * ndv_raw);
    const u64 ONE2   = pk2(1.0f, 1.0f);
    const u64 NEG1_2 = pk2(-1.0f, -1.0f);
    const u64 EPS2   = pk2(EPSF, EPSF);
    const u64 TINY2  = pk2(1e-24f, 1e-24f);
    // sqrt(pi) fold: DD' = sqrt(pi)*DD ; DEN1 = DD'^2 + EPS
    const float qsp  = SQPIF * 0.25f * a2m1;
    const u64 A2M1QP2 = pk2(qsp, qsp);
    const u64 SQPI2   = pk2(SQPIF, SQPIF);
    const u64 C2_2   = pk2(c2, c2);
    const u64 C1_2   = pk2(c1, c1);
    const u64 C0_2   = pk2(c0, c0);
    const u64 A2GV2  = pk2(a2Gv, a2Gv);
    const u64 F0R2 = pk2(f0r, f0r), F0G2 = pk2(f0g, f0g), F0B2 = pk2(f0b, f0b);
    const u64 DR2 = pk2(dR, dR), DG2 = pk2(dG, dG), DB2 = pk2(dB, dB);

    const ulonglong2* __restrict__ tb = g_tab + 3 * lane;

    u64 ACR = 0ull, ACG = 0ull, ACB = 0ull;   // packed (0.f, 0.f)

    #pragma unroll
    for (int kIt = 0; kIt < MH_ / 32; ++kIt) {
        // table loads: L1-resident (12KB shared by all warps), immediate offsets
        const ulonglong2 t0 = tb[3 * 32 * kIt + 0];
        const ulonglong2 t1 = tb[3 * 32 * kIt + 1];
        const ulonglong2 t2 = tb[3 * 32 * kIt + 2];
        const u64 VIS = visv[kIt];
        const u64 LX = t0.x, LY = t0.y;   // 0.5*l components
        const u64 LZ = t1.x, LR = t1.y;
        const u64 LG = t2.x, LB = t2.y;

        // half vector at half scale: H' = 0.5*(v+l); HH' = |h|^2/4 (exact scaling)
        const u64 HX = add2(LX, VX2);
        const u64 HY = add2(LY, VY2);
        const u64 HZ = add2(LZ, VZ2);
        const u64 HH = fma2(HX, HX, fma2(HY, HY, mul2(HZ, HZ)));
        const u64 HHc = add2(HH, TINY2);
        const float2 hh = upk2(HHc);
        const u64 HINV = pk2(rsq_fast(hh.x), rsq_fast(hh.y));   // = 2/|h| exactly

        // NL' = (n.l)/2 ; A = NL'+|NL'| = max(n.l,0) ; NdotL = A + EPS
        const u64 NL  = fma2(LX, NX2, fma2(LY, NY2, mul2(LZ, NZ2)));
        const u64 NDL = add2(add2(NL, NL & ABSM), EPS2);

        // n.h at half scale: NHR' = (n.l + n.v)/2 ; NH = NHR'*HINV = NdotH exactly
        const u64 NHR = add2(NL, NDVRH2);
        const u64 NH  = mul2(NHR, HINV);
        const u64 SSx = add2(NH, NH & ABSM);       // 2*max(NdotH,0)
        const u64 SS2 = mul2(SSx, SSx);
        const u64 DDp = fma2(SS2, A2M1QP2, SQPI2); // sqrt(pi)*(q*SS^2 + 1)
        const u64 DEN1 = fma2(DDp, DDp, EPS2);     // pi*DD^2 + EPS

        const u64 DEN23 = fma2(fma2(C2_2, NDL, C1_2), NDL, C0_2);
        const u64 DEN   = mul2(DEN1, DEN23);
        const float2 dv = upk2(DEN);
        const u64 RCPD  = pk2(rcp_fast(dv.x), rcp_fast(dv.y));
        const u64 S     = mul2(mul2(A2GV2, NDL), RCPD);

        // Fresnel: VdotH = |h|/2 = HHc'*HINV' exactly; t = 1 - VdotH
        const u64 VHs = mul2(HHc, HINV);
        const u64 Tt  = fma2(VHs, NEG1_2, ONE2);
        const u64 T2  = mul2(Tt, Tt);
        const u64 P5  = mul2(mul2(T2, T2), Tt);
        const u64 OMP5 = fma2(P5, NEG1_2, ONE2);   // 1 - p5 (shared by RGB)

        const u64 Wt = mul2(VIS, NDL);   // sa pre-folded into Li tables

        // FrC = f0C*(1-p5) + p5 ; S - dC = fma(dC, -1, S)
        const u64 FR = fma2(F0R2, OMP5, P5);
        const u64 FG = fma2(F0G2, OMP5, P5);
        const u64 FB = fma2(F0B2, OMP5, P5);
        const u64 SMR = fma2(DR2, NEG1_2, S);
        const u64 SMG = fma2(DG2, NEG1_2, S);
        const u64 SMB = fma2(DB2, NEG1_2, S);

        ACR = fma2(mul2(LR, Wt), fma2(FR, SMR, DR2), ACR);
        ACG = fma2(mul2(LG, Wt), fma2(FG, SMG, DG2), ACG);
        ACB = fma2(mul2(LB, Wt), fma2(FB, SMB, DB2), ACB);
    }

    // collapse packed halves, then warp tree-reduce
    const float2 cr = upk2(ACR);
    const float2 cg = upk2(ACG);
    const float2 cb = upk2(ACB);
    float accR = cr.x + cr.y;
    float accG = cg.x + cg.y;
    float accB = cb.x + cb.y;

    #pragma unroll
    for (int off = 16; off > 0; off >>= 1) {
        accR += __shfl_down_sync(0xffffffffu, accR, off);
        accG += __shfl_down_sync(0xffffffffu, accG, off);
        accB += __shfl_down_sync(0xffffffffu, accB, off);
    }

    if (lane == 0) {
        float* o = out + gwarp * 3;
        o[0] = accR;
        o[1] = accG;
        o[2] = accB;
    }
}

extern "C" void kernel_launch(void* const* d_in, const int* in_sizes, int n_in,
                              void* d_out, int out_size)
{
    const float* normals    = (const float*)d_in[0];
    const float* albedo     = (const float*)d_in[1];
    const float* metallic   = (const float*)d_in[2];
    const float* smoothness = (const float*)d_in[3];
    const float* viewdirs   = (const float*)d_in[4];
    const float* env_vis    = (const float*)d_in[5];
    const float* env_map    = (const float*)d_in[6];
    float* out = (float*)d_out;

    hdr_prep_kernel<<<8, 32>>>(env_map);    // parallel prep, MUFU sin/cos

    const int pairs   = N_ * V_;                // 8192 warps
    const int threads = 64;                     // 2 warps/block: finer tail granularity
    const int blocks  = pairs * 32 / threads;   // 4096

    hdr_render_kernel<<<blocks, threads>>>(normals, albedo, metallic, smoothness,
                                           viewdirs, env_vis, out);
}